// round 16
// baseline (speedup 1.0000x reference)
#include <cuda_runtime.h>
#include <cuda_fp16.h>
#include <math.h>
#include <stdint.h>

#define S_LEN 2048
#define HID   4096
#define NH    32
#define NKV   8
#define HD    128
#define WIN   1024
#define QDIM  4096
#define QKVN  6144
#define KVDIM 1024
#define MROWS 4096

typedef __half hlf;

__device__ hlf g_xh [(size_t)MROWS*HID];
__device__ hlf g_wf [(size_t)QKVN*HID];     // Wq|Wk|Wv
__device__ hlf g_woh[(size_t)HID*QDIM];
__device__ hlf g_qh [(size_t)MROWS*QDIM];
__device__ hlf g_kh [(size_t)MROWS*KVDIM];
__device__ hlf g_vh [(size_t)MROWS*KVDIM];
__device__ hlf g_aoh[(size_t)MROWS*QDIM];
__device__ int g_ctr[2];

// ---------------- PTX helpers ----------------
__device__ __forceinline__ uint32_t s2u(const void* p){
    uint32_t a;
    asm("{ .reg .u64 t; cvta.to.shared.u64 t,%1; cvt.u32.u64 %0,t; }":"=r"(a):"l"(p));
    return a;
}
#define CPA(dst,src) asm volatile( \
    "cp.async.cg.shared.global [%0],[%1],16;" :: "r"(dst),"l"(src) : "memory")
#define CPA_COMMIT() asm volatile("cp.async.commit_group;" ::: "memory")
#define CPA_WAIT0()  asm volatile("cp.async.wait_group 0;" ::: "memory")
#define CPA_WAIT1()  asm volatile("cp.async.wait_group 1;" ::: "memory")

#define LDSM4(r,addr) asm volatile( \
    "ldmatrix.sync.aligned.m8n8.x4.shared.b16 {%0,%1,%2,%3},[%4];" \
    : "=r"((r)[0]),"=r"((r)[1]),"=r"((r)[2]),"=r"((r)[3]) : "r"(addr))
#define LDSM4T(r,addr) asm volatile( \
    "ldmatrix.sync.aligned.m8n8.x4.trans.shared.b16 {%0,%1,%2,%3},[%4];" \
    : "=r"((r)[0]),"=r"((r)[1]),"=r"((r)[2]),"=r"((r)[3]) : "r"(addr))

#define MMA_F16(c,a,b) asm volatile( \
    "mma.sync.aligned.m16n8k16.row.col.f32.f16.f16.f32 " \
    "{%0,%1,%2,%3},{%4,%5,%6,%7},{%8,%9},{%0,%1,%2,%3};" \
    : "+f"((c)[0]),"+f"((c)[1]),"+f"((c)[2]),"+f"((c)[3]) \
    : "r"((a)[0]),"r"((a)[1]),"r"((a)[2]),"r"((a)[3]),"r"((b)[0]),"r"((b)[1]))

__device__ __forceinline__ uint32_t h2u(__half2 h){ return *reinterpret_cast<uint32_t*>(&h); }

// ---------------------------------------------------------------------------
// GEMM core: CTA tile 128x128, 256 thr (8 warps 4m x 2n), BK=64, 3-stage.
// ---------------------------------------------------------------------------
#define GK      4096
#define NCH64   64
#define ROWB64  144
#define ARR64   18432
#define STG64_B 36864
#define GSMEM64 (3*STG64_B)   // 110592

static __device__ __forceinline__ void load_stage64(
    uint32_t sb, int stage, int kc, int m0, int n0, int tid,
    const hlf* __restrict__ A, const hlf* __restrict__ Bh)
{
    uint32_t st = sb + stage*STG64_B;
    #pragma unroll
    for (int it=0; it<4; ++it){
        int idx = tid + it*256;
        int r = idx>>3, ch = idx&7;
        uint32_t so = (uint32_t)(r*ROWB64 + ch*16);
        CPA(st+so,        A  + (size_t)(m0+r)*GK + kc + ch*8);
        CPA(st+ARR64+so,  Bh + (size_t)(n0+r)*GK + kc + ch*8);
    }
    CPA_COMMIT();
}

#define GEMM_MAIN64(A_, B_, m0_, n0_)                                          \
    load_stage64(sb,0,0, m0_,n0_,tid,A_,B_);                                   \
    load_stage64(sb,1,64,m0_,n0_,tid,A_,B_);                                   \
    {                                                                          \
        int stg = 0;                                                           \
        for (int c=0; c<NCH64; ++c){                                           \
            CPA_WAIT1();                                                       \
            __syncthreads();                                                   \
            if (c+2 < NCH64){                                                  \
                int ns = stg+2; if (ns>=3) ns-=3;                              \
                load_stage64(sb,ns,(c+2)*64, m0_,n0_,tid,A_,B_);               \
            } else CPA_COMMIT();                                               \
            const uint32_t st = sb + stg*STG64_B;                              \
            _Pragma("unroll")                                                  \
            for (int kk=0; kk<4; ++kk){                                        \
                uint32_t ah[2][4];                                             \
                _Pragma("unroll")                                              \
                for (int mt=0; mt<2; ++mt)                                     \
                    LDSM4(ah[mt], st + (a_row + mt*16)*ROWB64 + kk*32 + a_colb);\
                uint32_t bh[8][2];                                             \
                _Pragma("unroll")                                              \
                for (int p=0; p<4; ++p){                                       \
                    uint32_t ba = st + ARR64 + (b_row + p*16)*ROWB64 + kk*32 + b_colb;\
                    uint32_t r[4];                                             \
                    LDSM4(r, ba);                                              \
                    bh[2*p][0]=r[0]; bh[2*p][1]=r[1];                          \
                    bh[2*p+1][0]=r[2]; bh[2*p+1][1]=r[3];                      \
                }                                                              \
                _Pragma("unroll")                                              \
                for (int mt=0; mt<2; ++mt)                                     \
                    _Pragma("unroll")                                          \
                    for (int nt=0; nt<8; ++nt)                                 \
                        MMA_F16(acc[mt][nt], ah[mt], bh[nt]);                  \
            }                                                                  \
            if (++stg >= 3) stg = 0;                                           \
        }                                                                      \
    }

// ---------------------------------------------------------------------------
// Persistent QKV GEMM (work-stealing) with fused rope/convert epilogue.
// ---------------------------------------------------------------------------
__global__ void __launch_bounds__(256,2) gemm_qkv(
    const hlf* __restrict__ A, const hlf* __restrict__ Bh,
    hlf* __restrict__ qh, hlf* __restrict__ kh, hlf* __restrict__ vh)
{
    extern __shared__ __align__(128) char sm[];
    __shared__ int s_tile;
    const uint32_t sb = s2u(sm);
    float* fstage = reinterpret_cast<float*>(sm);
    const int tid = threadIdx.x, wid = tid>>5, lane = tid&31;
    const int wm = wid&3, wn = wid>>2;
    const int g = lane>>2, tg = lane&3;
    const float SCL2 = 0.08838834764831845f * 1.4426950408889634f;

    const uint32_t a_row  = (uint32_t)(wm*32 + (lane&15));
    const uint32_t a_colb = (uint32_t)((lane>>4)*16);
    const uint32_t b_row  = (uint32_t)(wn*64 + (lane&7) + ((lane>>4)<<3));
    const uint32_t b_colb = (uint32_t)(((lane>>3)&1)*16);

    for (;;){
        if (tid == 0) s_tile = atomicAdd(&g_ctr[0], 1);
        __syncthreads();
        const int tile = s_tile;
        if (tile >= 1536) break;
        const int m0 = (tile & 31)*128, n0 = (tile >> 5)*128;

        float acc[2][8][4];
        #pragma unroll
        for (int i=0;i<2;++i)
            #pragma unroll
            for (int j=0;j<8;++j){acc[i][j][0]=0;acc[i][j][1]=0;acc[i][j][2]=0;acc[i][j][3]=0;}

        GEMM_MAIN64(A, Bh, m0, n0)

        hlf* dst; int cbase, stride; float scale; bool isv = false;
        if (n0 < 4096)      { dst = qh; cbase = n0;        stride = QDIM;  scale = SCL2; }
        else if (n0 < 5120) { dst = kh; cbase = n0 - 4096; stride = KVDIM; scale = 1.0f; }
        else                { dst = vh; cbase = n0 - 5120; stride = KVDIM; scale = 1.0f; isv = true; }

        #pragma unroll
        for (int mh=0; mh<2; ++mh){
            __syncthreads();
            if ((wm>>1) == mh){
                int rbase = (wm&1)*32;
                #pragma unroll
                for (int mt=0; mt<2; ++mt)
                    #pragma unroll
                    for (int nt=0; nt<8; ++nt){
                        int r = rbase + mt*16 + g;
                        int cc = wn*64 + nt*8 + tg*2;
                        fstage[r*132+cc]       = acc[mt][nt][0];
                        fstage[r*132+cc+1]     = acc[mt][nt][1];
                        fstage[(r+8)*132+cc]   = acc[mt][nt][2];
                        fstage[(r+8)*132+cc+1] = acc[mt][nt][3];
                    }
            }
            __syncthreads();

            #pragma unroll
            for (int it=0; it<16; ++it){
                int idx = tid + it*256;
                int r = idx >> 6, i = idx & 63;
                float x1 = fstage[r*132 + i], x2 = fstage[r*132 + i + 64];
                float y1, y2;
                if (isv){ y1 = x1; y2 = x2; }
                else {
                    int row = m0 + mh*64 + r;
                    int s = row & (S_LEN-1);
                    float inv = powf(10000.0f, -(float)i*(1.0f/64.0f));
                    float sn, cs; sincosf((float)s*inv, &sn, &cs);
                    y1 = (x1*cs - x2*sn)*scale;
                    y2 = (x2*cs + x1*sn)*scale;
                }
                size_t o = (size_t)(m0 + mh*64 + r)*stride + cbase + i;
                dst[o]      = __float2half_rn(y1);
                dst[o + 64] = __float2half_rn(y2);
            }
        }
    }
}

// ---------------------------------------------------------------------------
// Persistent O-projection GEMM (work-stealing, fp32 out).
// ---------------------------------------------------------------------------
__global__ void __launch_bounds__(256,2) gemm_out(
    const hlf* __restrict__ A, const hlf* __restrict__ Bh,
    float* __restrict__ C)
{
    extern __shared__ __align__(128) char sm[];
    __shared__ int s_tile;
    const uint32_t sb = s2u(sm);
    const int tid = threadIdx.x, wid = tid>>5, lane = tid&31;
    const int wm = wid&3, wn = wid>>2;
    const int g = lane>>2, tg = lane&3;

    const uint32_t a_row  = (uint32_t)(wm*32 + (lane&15));
    const uint32_t a_colb = (uint32_t)((lane>>4)*16);
    const uint32_t b_row  = (uint32_t)(wn*64 + (lane&7) + ((lane>>4)<<3));
    const uint32_t b_colb = (uint32_t)(((lane>>3)&1)*16);

    for (;;){
        if (tid == 0) s_tile = atomicAdd(&g_ctr[1], 1);
        __syncthreads();
        const int tile = s_tile;
        if (tile >= 1024) break;
        const int m0 = (tile & 31)*128, n0 = (tile >> 5)*128;

        float acc[2][8][4];
        #pragma unroll
        for (int i=0;i<2;++i)
            #pragma unroll
            for (int j=0;j<8;++j){acc[i][j][0]=0;acc[i][j][1]=0;acc[i][j][2]=0;acc[i][j][3]=0;}

        GEMM_MAIN64(A, Bh, m0, n0)

        #pragma unroll
        for (int mt=0; mt<2; ++mt)
            #pragma unroll
            for (int nt=0; nt<8; ++nt){
                int row = m0 + wm*32 + mt*16 + g;
                int col = n0 + wn*64 + nt*8 + tg*2;
                float2 v0 = {acc[mt][nt][0], acc[mt][nt][1]};
                float2 v1 = {acc[mt][nt][2], acc[mt][nt][3]};
                *(float2*)&C[(size_t)row*QDIM + col]     = v0;
                *(float2*)&C[(size_t)(row+8)*QDIM + col] = v1;
            }
    }
}

// ---------------------------------------------------------------------------
// conversion kernels: main (X,Wq,Wk,Wv; resets counters) + Wo (overlap stream)
// ---------------------------------------------------------------------------
__global__ void conv_main(const float* __restrict__ X,  const float* __restrict__ Wq,
                          const float* __restrict__ Wk, const float* __restrict__ Wv,
                          hlf* __restrict__ xh, hlf* __restrict__ wf)
{
    if (blockIdx.x == 0 && threadIdx.x == 0){ g_ctr[0] = 0; g_ctr[1] = 0; }
    const size_t QW  = (size_t)QDIM*HID;
    const size_t KVW = (size_t)1024*HID;
    int bid = blockIdx.x;
    const float* src; hlf* dst; int rel;
    if      (bid <  4096){ src = X;  dst = xh;             rel = bid; }
    else if (bid <  8192){ src = Wq; dst = wf;             rel = bid-4096; }
    else if (bid <  9216){ src = Wk; dst = wf + QW;        rel = bid-8192; }
    else                 { src = Wv; dst = wf + QW + KVW;  rel = bid-9216; }
    size_t i = ((size_t)rel*256 + threadIdx.x)*16;
    float4 v0 = *(const float4*)(src+i);
    float4 v1 = *(const float4*)(src+i+4);
    float4 v2 = *(const float4*)(src+i+8);
    float4 v3 = *(const float4*)(src+i+12);
    uint2 o0, o1;
    o0.x = h2u(__floats2half2_rn(v0.x, v0.y)); o0.y = h2u(__floats2half2_rn(v0.z, v0.w));
    o1.x = h2u(__floats2half2_rn(v1.x, v1.y)); o1.y = h2u(__floats2half2_rn(v1.z, v1.w));
    *(uint2*)&dst[i]   = o0;
    *(uint2*)&dst[i+4] = o1;
    o0.x = h2u(__floats2half2_rn(v2.x, v2.y)); o0.y = h2u(__floats2half2_rn(v2.z, v2.w));
    o1.x = h2u(__floats2half2_rn(v3.x, v3.y)); o1.y = h2u(__floats2half2_rn(v3.z, v3.w));
    *(uint2*)&dst[i+8]  = o0;
    *(uint2*)&dst[i+12] = o1;
}

__global__ void conv_wo(const float* __restrict__ Wo, hlf* __restrict__ woh)
{
    size_t i = ((size_t)blockIdx.x*256 + threadIdx.x)*16;
    float4 v0 = *(const float4*)(Wo+i);
    float4 v1 = *(const float4*)(Wo+i+4);
    float4 v2 = *(const float4*)(Wo+i+8);
    float4 v3 = *(const float4*)(Wo+i+12);
    uint2 o0, o1;
    o0.x = h2u(__floats2half2_rn(v0.x, v0.y)); o0.y = h2u(__floats2half2_rn(v0.z, v0.w));
    o1.x = h2u(__floats2half2_rn(v1.x, v1.y)); o1.y = h2u(__floats2half2_rn(v1.z, v1.w));
    *(uint2*)&woh[i]   = o0;
    *(uint2*)&woh[i+4] = o1;
    o0.x = h2u(__floats2half2_rn(v2.x, v2.y)); o0.y = h2u(__floats2half2_rn(v2.z, v2.w));
    o1.x = h2u(__floats2half2_rn(v3.x, v3.y)); o1.y = h2u(__floats2half2_rn(v3.z, v3.w));
    *(uint2*)&woh[i+8]  = o0;
    *(uint2*)&woh[i+12] = o1;
}

// ---------------------------------------------------------------------------
// fp16 HMMA flash attention — 2 CTAs/SM, single barrier per k-tile
// ---------------------------------------------------------------------------
#define AROWB 272
#define QSZ   34816
#define KVARR 17408
#define KVSTG 34816
#define ASMEM (QSZ + 2*KVSTG)   // 104448

static __device__ __forceinline__ void a_load_kv(
    uint32_t st, int kbase, int brow, int tid, int kvh,
    const hlf* __restrict__ kh, const hlf* __restrict__ vh)
{
    #pragma unroll
    for (int it=0; it<4; ++it){
        int idx = tid + it*256;
        int r = idx>>4, ch = idx&15;
        uint32_t so = (uint32_t)(r*AROWB + ch*16);
        size_t gsrc = (size_t)(brow + kbase + r)*KVDIM + kvh*HD + ch*8;
        CPA(st + so,         kh + gsrc);
        CPA(st + KVARR + so, vh + gsrc);
    }
    CPA_COMMIT();
}

__global__ void __launch_bounds__(256,2) attn_mma(
    const hlf* __restrict__ qh_, const hlf* __restrict__ kh_,
    const hlf* __restrict__ vh_, hlf* __restrict__ aoh)
{
    extern __shared__ __align__(128) char sm[];
    const uint32_t sb = s2u(sm);
    const uint32_t QH = sb, ST0 = sb + QSZ;

    const int tid = threadIdx.x, w = tid>>5, lane = tid&31;
    const int qb = (int)(gridDim.x - 1 - blockIdx.x);
    const int hh = blockIdx.y, b = blockIdx.z;
    const int q0 = qb*128, kvh = hh>>2;
    const int g = lane>>2, colc = (lane&3)*2;
    const int browg = b*S_LEN;

    #pragma unroll
    for (int it=0; it<8; ++it){
        int idx = tid + it*256;
        int r = idx>>4, ch = idx&15;
        uint32_t so = (uint32_t)(r*AROWB + ch*16);
        CPA(QH + so, qh_ + (size_t)(browg + q0 + r)*QDIM + hh*HD + ch*8);
    }
    CPA_COMMIT();

    int lo = q0 - (WIN-1); if (lo < 0) lo = 0;
    const int kt0 = lo >> 6, ktend = 2*qb + 1;

    a_load_kv(ST0, kt0*64, browg, tid, kvh, kh_, vh_);

    float O[16][4];
    #pragma unroll
    for (int t=0;t<16;++t){O[t][0]=0;O[t][1]=0;O[t][2]=0;O[t][3]=0;}
    float m0 = -1e30f, m1 = -1e30f, l0 = 0.f, l1 = 0.f;

    const uint32_t a_row  = (uint32_t)(w*16 + (lane&15));
    const uint32_t a_colb = (uint32_t)((lane>>4)*16);
    const uint32_t kb_row = (uint32_t)((lane&7) + ((lane>>4)<<3));
    const uint32_t kb_col = (uint32_t)(((lane>>3)&1)*16);
    const uint32_t vb_row = (uint32_t)((lane&7) + (lane&8));
    const uint32_t vb_col = (uint32_t)((lane>>4)*16);

    const int rmin_w = q0 + w*16;

    for (int kt = kt0; kt <= ktend; ++kt){
        const int s = (kt - kt0) & 1;
        const uint32_t ST = ST0 + (uint32_t)s*KVSTG;

        // single barrier per tile: all groups arrived + other buffer consumed
        CPA_WAIT0();
        __syncthreads();
        if (kt < ktend)
            a_load_kv(ST0 + (uint32_t)(s^1)*KVSTG, (kt+1)*64, browg, tid, kvh, kh_, vh_);

        const int kbase = kt*64;
        if ((kbase <= rmin_w + 15) && (kbase + 63 > rmin_w - WIN)){
            // ---- S = Q K^T, two 4-step passes (Q frags from smem) ----
            float p[8][4];
            #pragma unroll
            for (int t=0;t<8;++t){p[t][0]=0;p[t][1]=0;p[t][2]=0;p[t][3]=0;}
            #pragma unroll
            for (int half=0; half<2; ++half){
                uint32_t qf[4][4];
                #pragma unroll
                for (int kk=0; kk<4; ++kk)
                    LDSM4(qf[kk], QH + a_row*AROWB + (half*4+kk)*32 + a_colb);
                #pragma unroll
                for (int kk=0; kk<4; ++kk){
                    #pragma unroll
                    for (int np=0; np<4; ++np){
                        uint32_t kf[4];
                        LDSM4(kf, ST + (np*16 + kb_row)*AROWB + (half*4+kk)*32 + kb_col);
                        MMA_F16(p[2*np],   qf[kk], kf);
                        MMA_F16(p[2*np+1], qf[kk], kf+2);
                    }
                }
            }

            const int r0 = rmin_w + g, r1 = r0 + 8;
            const bool full = (kbase + 63 <= rmin_w) && (kbase >= rmin_w + 16 - WIN);
            if (!full){
                #pragma unroll
                for (int t=0; t<8; ++t){
                    #pragma unroll
                    for (int e=0; e<2; ++e){
                        int kj = kbase + t*8 + colc + e;
                        if (!((kj<=r0)&&(r0-kj<WIN))) p[t][e]   = -1e30f;
                        if (!((kj<=r1)&&(r1-kj<WIN))) p[t][2+e] = -1e30f;
                    }
                }
            }
            float rm0 = -1e30f, rm1 = -1e30f;
            #pragma unroll
            for (int t=0; t<8; ++t){
                rm0 = fmaxf(rm0, fmaxf(p[t][0], p[t][1]));
                rm1 = fmaxf(rm1, fmaxf(p[t][2], p[t][3]));
            }
            rm0 = fmaxf(rm0, __shfl_xor_sync(~0u, rm0, 1));
            rm0 = fmaxf(rm0, __shfl_xor_sync(~0u, rm0, 2));
            rm1 = fmaxf(rm1, __shfl_xor_sync(~0u, rm1, 1));
            rm1 = fmaxf(rm1, __shfl_xor_sync(~0u, rm1, 2));
            float mn0 = fmaxf(m0, rm0), mn1 = fmaxf(m1, rm1);
            float sc0 = exp2f(m0 - mn0), sc1 = exp2f(m1 - mn1);
            m0 = mn0; m1 = mn1;

            uint32_t eh0[8], eh1[8];
            float rs0 = 0.f, rs1 = 0.f;
            #pragma unroll
            for (int t=0; t<8; ++t){
                uint32_t d0 = h2u(__floats2half2_rn(p[t][0]-mn0, p[t][1]-mn0));
                uint32_t d1 = h2u(__floats2half2_rn(p[t][2]-mn1, p[t][3]-mn1));
                asm("ex2.approx.f16x2 %0,%1;" : "=r"(eh0[t]) : "r"(d0));
                asm("ex2.approx.f16x2 %0,%1;" : "=r"(eh1[t]) : "r"(d1));
                float2 f0 = __half22float2(*reinterpret_cast<__half2*>(&eh0[t]));
                float2 f1 = __half22float2(*reinterpret_cast<__half2*>(&eh1[t]));
                rs0 += f0.x + f0.y;
                rs1 += f1.x + f1.y;
            }
            rs0 += __shfl_xor_sync(~0u, rs0, 1); rs0 += __shfl_xor_sync(~0u, rs0, 2);
            rs1 += __shfl_xor_sync(~0u, rs1, 1); rs1 += __shfl_xor_sync(~0u, rs1, 2);
            l0 = l0*sc0 + rs0; l1 = l1*sc1 + rs1;

            if (!__all_sync(~0u, (sc0==1.0f) && (sc1==1.0f))){
                #pragma unroll
                for (int t=0; t<16; ++t){
                    O[t][0]*=sc0; O[t][1]*=sc0; O[t][2]*=sc1; O[t][3]*=sc1;
                }
            }

            const uint32_t VB = ST + KVARR;
            #pragma unroll
            for (int kk=0; kk<4; ++kk){
                uint32_t pha[4];
                pha[0] = eh0[2*kk];   pha[1] = eh1[2*kk];
                pha[2] = eh0[2*kk+1]; pha[3] = eh1[2*kk+1];
                #pragma unroll
                for (int vp=0; vp<8; ++vp){
                    uint32_t vf[4];
                    LDSM4T(vf, VB + (kk*16 + vb_row)*AROWB + vp*32 + vb_col);
                    MMA_F16(O[2*vp],   pha, vf);
                    MMA_F16(O[2*vp+1], pha, vf+2);
                }
            }
        }
    }

    float il0 = 1.0f/l0, il1 = 1.0f/l1;
    const size_t row0 = (size_t)(browg + q0 + w*16 + g);
    #pragma unroll
    for (int nt=0; nt<16; ++nt){
        size_t o0 = row0*QDIM + hh*HD + nt*8 + colc;
        size_t o1 = o0 + 8*QDIM;
        *(uint32_t*)&aoh[o0] = h2u(__floats2half2_rn(O[nt][0]*il0, O[nt][1]*il0));
        *(uint32_t*)&aoh[o1] = h2u(__floats2half2_rn(O[nt][2]*il1, O[nt][3]*il1));
    }
}

// ---------------------------------------------------------------------------
extern "C" void kernel_launch(void* const* d_in, const int* in_sizes, int n_in,
                              void* d_out, int out_size)
{
    const float* X  = (const float*)d_in[0];
    const float* Wq = (const float*)d_in[1];
    const float* Wk = (const float*)d_in[2];
    const float* Wv = (const float*)d_in[3];
    const float* Wo = (const float*)d_in[4];
    float* out = (float*)d_out;

    hlf *xh,*wf,*woh,*qh,*kh,*vh,*aoh;
    cudaGetSymbolAddress((void**)&xh, g_xh);
    cudaGetSymbolAddress((void**)&wf, g_wf);
    cudaGetSymbolAddress((void**)&woh,g_woh);
    cudaGetSymbolAddress((void**)&qh, g_qh);
    cudaGetSymbolAddress((void**)&kh, g_kh);
    cudaGetSymbolAddress((void**)&vh, g_vh);
    cudaGetSymbolAddress((void**)&aoh,g_aoh);

    static cudaStream_t s2 = nullptr;
    static cudaEvent_t evF = nullptr, evJ = nullptr;
    if (!s2){
        cudaStreamCreateWithFlags(&s2, cudaStreamNonBlocking);
        cudaEventCreateWithFlags(&evF, cudaEventDisableTiming);
        cudaEventCreateWithFlags(&evJ, cudaEventDisableTiming);
    }

    // main-stream conversions (X + QKV weights); resets tile counters
    conv_main<<<10240, 256>>>(X, Wq, Wk, Wv, xh, wf);

    // fork: convert Wo on side stream, overlapping gemm_qkv/attention
    cudaEventRecord(evF, 0);
    cudaStreamWaitEvent(s2, evF, 0);
    conv_wo<<<4096, 256, 0, s2>>>(Wo, woh);
    cudaEventRecord(evJ, s2);

    cudaFuncSetAttribute(gemm_qkv, cudaFuncAttributeMaxDynamicSharedMemorySize, GSMEM64);
    gemm_qkv<<<296, 256, GSMEM64>>>(xh, wf, qh, kh, vh);

    cudaFuncSetAttribute(attn_mma, cudaFuncAttributeMaxDynamicSharedMemorySize, ASMEM);
    attn_mma<<<dim3(S_LEN/128, NH, 2), 256, ASMEM>>>(qh, kh, vh, aoh);

    // join before O projection
    cudaStreamWaitEvent(0, evJ, 0);
    cudaFuncSetAttribute(gemm_out, cudaFuncAttributeMaxDynamicSharedMemorySize, GSMEM64);
    gemm_out<<<296, 256, GSMEM64>>>(aoh, woh, out);
}

// round 17
// speedup vs baseline: 1.0442x; 1.0442x over previous
#include <cuda_runtime.h>
#include <cuda_fp16.h>
#include <math.h>
#include <stdint.h>

#define S_LEN 2048
#define HID   4096
#define NH    32
#define NKV   8
#define HD    128
#define WIN   1024
#define QDIM  4096
#define QKVN  6144
#define KVDIM 1024
#define MROWS 4096

typedef __half hlf;

__device__ hlf g_xh [(size_t)MROWS*HID];
__device__ hlf g_wf [(size_t)QKVN*HID];     // Wq|Wk|Wv
__device__ hlf g_woh[(size_t)HID*QDIM];
__device__ hlf g_qh [(size_t)MROWS*QDIM];
__device__ hlf g_kh [(size_t)MROWS*KVDIM];
__device__ hlf g_vh [(size_t)MROWS*KVDIM];
__device__ hlf g_aoh[(size_t)MROWS*QDIM];
__device__ int g_ctr[2];

// ---------------- PTX helpers ----------------
__device__ __forceinline__ uint32_t s2u(const void* p){
    uint32_t a;
    asm("{ .reg .u64 t; cvta.to.shared.u64 t,%1; cvt.u32.u64 %0,t; }":"=r"(a):"l"(p));
    return a;
}
#define CPA(dst,src) asm volatile( \
    "cp.async.cg.shared.global [%0],[%1],16;" :: "r"(dst),"l"(src) : "memory")
#define CPA_COMMIT() asm volatile("cp.async.commit_group;" ::: "memory")
#define CPA_WAIT0()  asm volatile("cp.async.wait_group 0;" ::: "memory")
#define CPA_WAIT1()  asm volatile("cp.async.wait_group 1;" ::: "memory")

#define LDSM4(r,addr) asm volatile( \
    "ldmatrix.sync.aligned.m8n8.x4.shared.b16 {%0,%1,%2,%3},[%4];" \
    : "=r"((r)[0]),"=r"((r)[1]),"=r"((r)[2]),"=r"((r)[3]) : "r"(addr))
#define LDSM4T(r,addr) asm volatile( \
    "ldmatrix.sync.aligned.m8n8.x4.trans.shared.b16 {%0,%1,%2,%3},[%4];" \
    : "=r"((r)[0]),"=r"((r)[1]),"=r"((r)[2]),"=r"((r)[3]) : "r"(addr))

#define MMA_F16(c,a,b) asm volatile( \
    "mma.sync.aligned.m16n8k16.row.col.f32.f16.f16.f32 " \
    "{%0,%1,%2,%3},{%4,%5,%6,%7},{%8,%9},{%0,%1,%2,%3};" \
    : "+f"((c)[0]),"+f"((c)[1]),"+f"((c)[2]),"+f"((c)[3]) \
    : "r"((a)[0]),"r"((a)[1]),"r"((a)[2]),"r"((a)[3]),"r"((b)[0]),"r"((b)[1]))

__device__ __forceinline__ uint32_t h2u(__half2 h){ return *reinterpret_cast<uint32_t*>(&h); }

// ---------------------------------------------------------------------------
// GEMM core: CTA tile 128x128, 256 thr (8 warps 4m x 2n), BK=64, 3-stage.
// Inner loop: A-fragment prefetch one kk-step ahead.
// ---------------------------------------------------------------------------
#define GK      4096
#define NCH64   64
#define ROWB64  144
#define ARR64   18432
#define STG64_B 36864
#define GSMEM64 (3*STG64_B)   // 110592

static __device__ __forceinline__ void load_stage64(
    uint32_t sb, int stage, int kc, int m0, int n0, int tid,
    const hlf* __restrict__ A, const hlf* __restrict__ Bh)
{
    uint32_t st = sb + stage*STG64_B;
    #pragma unroll
    for (int it=0; it<4; ++it){
        int idx = tid + it*256;
        int r = idx>>3, ch = idx&7;
        uint32_t so = (uint32_t)(r*ROWB64 + ch*16);
        CPA(st+so,        A  + (size_t)(m0+r)*GK + kc + ch*8);
        CPA(st+ARR64+so,  Bh + (size_t)(n0+r)*GK + kc + ch*8);
    }
    CPA_COMMIT();
}

#define GEMM_MAIN64(A_, B_, m0_, n0_)                                          \
    load_stage64(sb,0,0, m0_,n0_,tid,A_,B_);                                   \
    load_stage64(sb,1,64,m0_,n0_,tid,A_,B_);                                   \
    {                                                                          \
        int stg = 0;                                                           \
        for (int c=0; c<NCH64; ++c){                                           \
            CPA_WAIT1();                                                       \
            __syncthreads();                                                   \
            if (c+2 < NCH64){                                                  \
                int ns = stg+2; if (ns>=3) ns-=3;                              \
                load_stage64(sb,ns,(c+2)*64, m0_,n0_,tid,A_,B_);               \
            } else CPA_COMMIT();                                               \
            const uint32_t st = sb + stg*STG64_B;                              \
            uint32_t ah[2][4];                                                 \
            _Pragma("unroll")                                                  \
            for (int mt=0; mt<2; ++mt)                                         \
                LDSM4(ah[mt], st + (a_row + mt*16)*ROWB64 + a_colb);           \
            _Pragma("unroll")                                                  \
            for (int kk=0; kk<4; ++kk){                                        \
                uint32_t bh[8][2];                                             \
                _Pragma("unroll")                                              \
                for (int p=0; p<4; ++p){                                       \
                    uint32_t ba = st + ARR64 + (b_row + p*16)*ROWB64 + kk*32 + b_colb;\
                    uint32_t r[4];                                             \
                    LDSM4(r, ba);                                              \
                    bh[2*p][0]=r[0]; bh[2*p][1]=r[1];                          \
                    bh[2*p+1][0]=r[2]; bh[2*p+1][1]=r[3];                      \
                }                                                              \
                uint32_t an[2][4];                                             \
                if (kk < 3){                                                   \
                    _Pragma("unroll")                                          \
                    for (int mt=0; mt<2; ++mt)                                 \
                        LDSM4(an[mt], st + (a_row + mt*16)*ROWB64 + (kk+1)*32 + a_colb);\
                }                                                              \
                _Pragma("unroll")                                              \
                for (int mt=0; mt<2; ++mt)                                     \
                    _Pragma("unroll")                                          \
                    for (int nt=0; nt<8; ++nt)                                 \
                        MMA_F16(acc[mt][nt], ah[mt], bh[nt]);                  \
                if (kk < 3){                                                   \
                    _Pragma("unroll")                                          \
                    for (int mt=0; mt<2; ++mt)                                 \
                        _Pragma("unroll")                                      \
                        for (int e=0; e<4; ++e) ah[mt][e] = an[mt][e];         \
                }                                                              \
            }                                                                  \
            if (++stg >= 3) stg = 0;                                           \
        }                                                                      \
    }

// ---------------------------------------------------------------------------
// Persistent QKV GEMM (work-stealing) with fused rope/convert epilogue.
// ---------------------------------------------------------------------------
__global__ void __launch_bounds__(256,2) gemm_qkv(
    const hlf* __restrict__ A, const hlf* __restrict__ Bh,
    hlf* __restrict__ qh, hlf* __restrict__ kh, hlf* __restrict__ vh)
{
    extern __shared__ __align__(128) char sm[];
    __shared__ int s_tile;
    const uint32_t sb = s2u(sm);
    float* fstage = reinterpret_cast<float*>(sm);
    const int tid = threadIdx.x, wid = tid>>5, lane = tid&31;
    const int wm = wid&3, wn = wid>>2;
    const int g = lane>>2, tg = lane&3;
    const float SCL2 = 0.08838834764831845f * 1.4426950408889634f;

    const uint32_t a_row  = (uint32_t)(wm*32 + (lane&15));
    const uint32_t a_colb = (uint32_t)((lane>>4)*16);
    const uint32_t b_row  = (uint32_t)(wn*64 + (lane&7) + ((lane>>4)<<3));
    const uint32_t b_colb = (uint32_t)(((lane>>3)&1)*16);

    for (;;){
        if (tid == 0) s_tile = atomicAdd(&g_ctr[0], 1);
        __syncthreads();
        const int tile = s_tile;
        if (tile >= 1536) break;
        const int m0 = (tile & 31)*128, n0 = (tile >> 5)*128;

        float acc[2][8][4];
        #pragma unroll
        for (int i=0;i<2;++i)
            #pragma unroll
            for (int j=0;j<8;++j){acc[i][j][0]=0;acc[i][j][1]=0;acc[i][j][2]=0;acc[i][j][3]=0;}

        GEMM_MAIN64(A, Bh, m0, n0)

        hlf* dst; int cbase, stride; float scale; bool isv = false;
        if (n0 < 4096)      { dst = qh; cbase = n0;        stride = QDIM;  scale = SCL2; }
        else if (n0 < 5120) { dst = kh; cbase = n0 - 4096; stride = KVDIM; scale = 1.0f; }
        else                { dst = vh; cbase = n0 - 5120; stride = KVDIM; scale = 1.0f; isv = true; }

        #pragma unroll
        for (int mh=0; mh<2; ++mh){
            __syncthreads();
            if ((wm>>1) == mh){
                int rbase = (wm&1)*32;
                #pragma unroll
                for (int mt=0; mt<2; ++mt)
                    #pragma unroll
                    for (int nt=0; nt<8; ++nt){
                        int r = rbase + mt*16 + g;
                        int cc = wn*64 + nt*8 + tg*2;
                        fstage[r*132+cc]       = acc[mt][nt][0];
                        fstage[r*132+cc+1]     = acc[mt][nt][1];
                        fstage[(r+8)*132+cc]   = acc[mt][nt][2];
                        fstage[(r+8)*132+cc+1] = acc[mt][nt][3];
                    }
            }
            __syncthreads();

            #pragma unroll
            for (int it=0; it<16; ++it){
                int idx = tid + it*256;
                int r = idx >> 6, i = idx & 63;
                float x1 = fstage[r*132 + i], x2 = fstage[r*132 + i + 64];
                float y1, y2;
                if (isv){ y1 = x1; y2 = x2; }
                else {
                    int row = m0 + mh*64 + r;
                    int s = row & (S_LEN-1);
                    float inv = powf(10000.0f, -(float)i*(1.0f/64.0f));
                    float sn, cs; sincosf((float)s*inv, &sn, &cs);
                    y1 = (x1*cs - x2*sn)*scale;
                    y2 = (x2*cs + x1*sn)*scale;
                }
                size_t o = (size_t)(m0 + mh*64 + r)*stride + cbase + i;
                dst[o]      = __float2half_rn(y1);
                dst[o + 64] = __float2half_rn(y2);
            }
        }
    }
}

// ---------------------------------------------------------------------------
// Persistent O-projection GEMM (work-stealing, fp32 out).
// ---------------------------------------------------------------------------
__global__ void __launch_bounds__(256,2) gemm_out(
    const hlf* __restrict__ A, const hlf* __restrict__ Bh,
    float* __restrict__ C)
{
    extern __shared__ __align__(128) char sm[];
    __shared__ int s_tile;
    const uint32_t sb = s2u(sm);
    const int tid = threadIdx.x, wid = tid>>5, lane = tid&31;
    const int wm = wid&3, wn = wid>>2;
    const int g = lane>>2, tg = lane&3;

    const uint32_t a_row  = (uint32_t)(wm*32 + (lane&15));
    const uint32_t a_colb = (uint32_t)((lane>>4)*16);
    const uint32_t b_row  = (uint32_t)(wn*64 + (lane&7) + ((lane>>4)<<3));
    const uint32_t b_colb = (uint32_t)(((lane>>3)&1)*16);

    for (;;){
        if (tid == 0) s_tile = atomicAdd(&g_ctr[1], 1);
        __syncthreads();
        const int tile = s_tile;
        if (tile >= 1024) break;
        const int m0 = (tile & 31)*128, n0 = (tile >> 5)*128;

        float acc[2][8][4];
        #pragma unroll
        for (int i=0;i<2;++i)
            #pragma unroll
            for (int j=0;j<8;++j){acc[i][j][0]=0;acc[i][j][1]=0;acc[i][j][2]=0;acc[i][j][3]=0;}

        GEMM_MAIN64(A, Bh, m0, n0)

        #pragma unroll
        for (int mt=0; mt<2; ++mt)
            #pragma unroll
            for (int nt=0; nt<8; ++nt){
                int row = m0 + wm*32 + mt*16 + g;
                int col = n0 + wn*64 + nt*8 + tg*2;
                float2 v0 = {acc[mt][nt][0], acc[mt][nt][1]};
                float2 v1 = {acc[mt][nt][2], acc[mt][nt][3]};
                *(float2*)&C[(size_t)row*QDIM + col]     = v0;
                *(float2*)&C[(size_t)(row+8)*QDIM + col] = v1;
            }
    }
}

// ---------------------------------------------------------------------------
// fused fp32->fp16 conversion (one launch, main stream); resets counters
// ---------------------------------------------------------------------------
__global__ void conv_all(const float* __restrict__ X,  const float* __restrict__ Wq,
                         const float* __restrict__ Wk, const float* __restrict__ Wv,
                         const float* __restrict__ Wo,
                         hlf* __restrict__ xh, hlf* __restrict__ wf, hlf* __restrict__ woh)
{
    if (blockIdx.x == 0 && threadIdx.x == 0){ g_ctr[0] = 0; g_ctr[1] = 0; }
    const size_t QW  = (size_t)QDIM*HID;
    const size_t KVW = (size_t)1024*HID;
    int bid = blockIdx.x;
    const float* src; hlf* dst; int rel;
    if      (bid <  4096){ src = X;  dst = xh;             rel = bid; }
    else if (bid <  8192){ src = Wq; dst = wf;             rel = bid-4096; }
    else if (bid <  9216){ src = Wk; dst = wf + QW;        rel = bid-8192; }
    else if (bid < 10240){ src = Wv; dst = wf + QW + KVW;  rel = bid-9216; }
    else                 { src = Wo; dst = woh;            rel = bid-10240; }
    size_t i = ((size_t)rel*256 + threadIdx.x)*16;
    float4 v0 = *(const float4*)(src+i);
    float4 v1 = *(const float4*)(src+i+4);
    float4 v2 = *(const float4*)(src+i+8);
    float4 v3 = *(const float4*)(src+i+12);
    uint2 o0, o1;
    o0.x = h2u(__floats2half2_rn(v0.x, v0.y)); o0.y = h2u(__floats2half2_rn(v0.z, v0.w));
    o1.x = h2u(__floats2half2_rn(v1.x, v1.y)); o1.y = h2u(__floats2half2_rn(v1.z, v1.w));
    *(uint2*)&dst[i]   = o0;
    *(uint2*)&dst[i+4] = o1;
    o0.x = h2u(__floats2half2_rn(v2.x, v2.y)); o0.y = h2u(__floats2half2_rn(v2.z, v2.w));
    o1.x = h2u(__floats2half2_rn(v3.x, v3.y)); o1.y = h2u(__floats2half2_rn(v3.z, v3.w));
    *(uint2*)&dst[i+8]  = o0;
    *(uint2*)&dst[i+12] = o1;
}

// ---------------------------------------------------------------------------
// fp16 HMMA flash attention — 2 CTAs/SM, single barrier per k-tile
// ---------------------------------------------------------------------------
#define AROWB 272
#define QSZ   34816
#define KVARR 17408
#define KVSTG 34816
#define ASMEM (QSZ + 2*KVSTG)   // 104448

static __device__ __forceinline__ void a_load_kv(
    uint32_t st, int kbase, int brow, int tid, int kvh,
    const hlf* __restrict__ kh, const hlf* __restrict__ vh)
{
    #pragma unroll
    for (int it=0; it<4; ++it){
        int idx = tid + it*256;
        int r = idx>>4, ch = idx&15;
        uint32_t so = (uint32_t)(r*AROWB + ch*16);
        size_t gsrc = (size_t)(brow + kbase + r)*KVDIM + kvh*HD + ch*8;
        CPA(st + so,         kh + gsrc);
        CPA(st + KVARR + so, vh + gsrc);
    }
    CPA_COMMIT();
}

__global__ void __launch_bounds__(256,2) attn_mma(
    const hlf* __restrict__ qh_, const hlf* __restrict__ kh_,
    const hlf* __restrict__ vh_, hlf* __restrict__ aoh)
{
    extern __shared__ __align__(128) char sm[];
    const uint32_t sb = s2u(sm);
    const uint32_t QH = sb, ST0 = sb + QSZ;

    const int tid = threadIdx.x, w = tid>>5, lane = tid&31;
    const int qb = (int)(gridDim.x - 1 - blockIdx.x);
    const int hh = blockIdx.y, b = blockIdx.z;
    const int q0 = qb*128, kvh = hh>>2;
    const int g = lane>>2, colc = (lane&3)*2;
    const int browg = b*S_LEN;

    #pragma unroll
    for (int it=0; it<8; ++it){
        int idx = tid + it*256;
        int r = idx>>4, ch = idx&15;
        uint32_t so = (uint32_t)(r*AROWB + ch*16);
        CPA(QH + so, qh_ + (size_t)(browg + q0 + r)*QDIM + hh*HD + ch*8);
    }
    CPA_COMMIT();

    int lo = q0 - (WIN-1); if (lo < 0) lo = 0;
    const int kt0 = lo >> 6, ktend = 2*qb + 1;

    a_load_kv(ST0, kt0*64, browg, tid, kvh, kh_, vh_);

    float O[16][4];
    #pragma unroll
    for (int t=0;t<16;++t){O[t][0]=0;O[t][1]=0;O[t][2]=0;O[t][3]=0;}
    float m0 = -1e30f, m1 = -1e30f, l0 = 0.f, l1 = 0.f;

    const uint32_t a_row  = (uint32_t)(w*16 + (lane&15));
    const uint32_t a_colb = (uint32_t)((lane>>4)*16);
    const uint32_t kb_row = (uint32_t)((lane&7) + ((lane>>4)<<3));
    const uint32_t kb_col = (uint32_t)(((lane>>3)&1)*16);
    const uint32_t vb_row = (uint32_t)((lane&7) + (lane&8));
    const uint32_t vb_col = (uint32_t)((lane>>4)*16);

    const int rmin_w = q0 + w*16;

    for (int kt = kt0; kt <= ktend; ++kt){
        const int s = (kt - kt0) & 1;
        const uint32_t ST = ST0 + (uint32_t)s*KVSTG;

        CPA_WAIT0();
        __syncthreads();
        if (kt < ktend)
            a_load_kv(ST0 + (uint32_t)(s^1)*KVSTG, (kt+1)*64, browg, tid, kvh, kh_, vh_);

        const int kbase = kt*64;
        if ((kbase <= rmin_w + 15) && (kbase + 63 > rmin_w - WIN)){
            float p[8][4];
            #pragma unroll
            for (int t=0;t<8;++t){p[t][0]=0;p[t][1]=0;p[t][2]=0;p[t][3]=0;}
            #pragma unroll
            for (int half=0; half<2; ++half){
                uint32_t qf[4][4];
                #pragma unroll
                for (int kk=0; kk<4; ++kk)
                    LDSM4(qf[kk], QH + a_row*AROWB + (half*4+kk)*32 + a_colb);
                #pragma unroll
                for (int kk=0; kk<4; ++kk){
                    #pragma unroll
                    for (int np=0; np<4; ++np){
                        uint32_t kf[4];
                        LDSM4(kf, ST + (np*16 + kb_row)*AROWB + (half*4+kk)*32 + kb_col);
                        MMA_F16(p[2*np],   qf[kk], kf);
                        MMA_F16(p[2*np+1], qf[kk], kf+2);
                    }
                }
            }

            const int r0 = rmin_w + g, r1 = r0 + 8;
            const bool full = (kbase + 63 <= rmin_w) && (kbase >= rmin_w + 16 - WIN);
            if (!full){
                #pragma unroll
                for (int t=0; t<8; ++t){
                    #pragma unroll
                    for (int e=0; e<2; ++e){
                        int kj = kbase + t*8 + colc + e;
                        if (!((kj<=r0)&&(r0-kj<WIN))) p[t][e]   = -1e30f;
                        if (!((kj<=r1)&&(r1-kj<WIN))) p[t][2+e] = -1e30f;
                    }
                }
            }
            float rm0 = -1e30f, rm1 = -1e30f;
            #pragma unroll
            for (int t=0; t<8; ++t){
                rm0 = fmaxf(rm0, fmaxf(p[t][0], p[t][1]));
                rm1 = fmaxf(rm1, fmaxf(p[t][2], p[t][3]));
            }
            rm0 = fmaxf(rm0, __shfl_xor_sync(~0u, rm0, 1));
            rm0 = fmaxf(rm0, __shfl_xor_sync(~0u, rm0, 2));
            rm1 = fmaxf(rm1, __shfl_xor_sync(~0u, rm1, 1));
            rm1 = fmaxf(rm1, __shfl_xor_sync(~0u, rm1, 2));
            float mn0 = fmaxf(m0, rm0), mn1 = fmaxf(m1, rm1);
            float sc0 = exp2f(m0 - mn0), sc1 = exp2f(m1 - mn1);
            m0 = mn0; m1 = mn1;

            uint32_t eh0[8], eh1[8];
            float rs0 = 0.f, rs1 = 0.f;
            #pragma unroll
            for (int t=0; t<8; ++t){
                uint32_t d0 = h2u(__floats2half2_rn(p[t][0]-mn0, p[t][1]-mn0));
                uint32_t d1 = h2u(__floats2half2_rn(p[t][2]-mn1, p[t][3]-mn1));
                asm("ex2.approx.f16x2 %0,%1;" : "=r"(eh0[t]) : "r"(d0));
                asm("ex2.approx.f16x2 %0,%1;" : "=r"(eh1[t]) : "r"(d1));
                float2 f0 = __half22float2(*reinterpret_cast<__half2*>(&eh0[t]));
                float2 f1 = __half22float2(*reinterpret_cast<__half2*>(&eh1[t]));
                rs0 += f0.x + f0.y;
                rs1 += f1.x + f1.y;
            }
            rs0 += __shfl_xor_sync(~0u, rs0, 1); rs0 += __shfl_xor_sync(~0u, rs0, 2);
            rs1 += __shfl_xor_sync(~0u, rs1, 1); rs1 += __shfl_xor_sync(~0u, rs1, 2);
            l0 = l0*sc0 + rs0; l1 = l1*sc1 + rs1;

            if (!__all_sync(~0u, (sc0==1.0f) && (sc1==1.0f))){
                #pragma unroll
                for (int t=0; t<16; ++t){
                    O[t][0]*=sc0; O[t][1]*=sc0; O[t][2]*=sc1; O[t][3]*=sc1;
                }
            }

            const uint32_t VB = ST + KVARR;
            #pragma unroll
            for (int kk=0; kk<4; ++kk){
                uint32_t pha[4];
                pha[0] = eh0[2*kk];   pha[1] = eh1[2*kk];
                pha[2] = eh0[2*kk+1]; pha[3] = eh1[2*kk+1];
                #pragma unroll
                for (int vp=0; vp<8; ++vp){
                    uint32_t vf[4];
                    LDSM4T(vf, VB + (kk*16 + vb_row)*AROWB + vp*32 + vb_col);
                    MMA_F16(O[2*vp],   pha, vf);
                    MMA_F16(O[2*vp+1], pha, vf+2);
                }
            }
        }
    }

    float il0 = 1.0f/l0, il1 = 1.0f/l1;
    const size_t row0 = (size_t)(browg + q0 + w*16 + g);
    #pragma unroll
    for (int nt=0; nt<16; ++nt){
        size_t o0 = row0*QDIM + hh*HD + nt*8 + colc;
        size_t o1 = o0 + 8*QDIM;
        *(uint32_t*)&aoh[o0] = h2u(__floats2half2_rn(O[nt][0]*il0, O[nt][1]*il0));
        *(uint32_t*)&aoh[o1] = h2u(__floats2half2_rn(O[nt][2]*il1, O[nt][3]*il1));
    }
}

// ---------------------------------------------------------------------------
extern "C" void kernel_launch(void* const* d_in, const int* in_sizes, int n_in,
                              void* d_out, int out_size)
{
    const float* X  = (const float*)d_in[0];
    const float* Wq = (const float*)d_in[1];
    const float* Wk = (const float*)d_in[2];
    const float* Wv = (const float*)d_in[3];
    const float* Wo = (const float*)d_in[4];
    float* out = (float*)d_out;

    hlf *xh,*wf,*woh,*qh,*kh,*vh,*aoh;
    cudaGetSymbolAddress((void**)&xh, g_xh);
    cudaGetSymbolAddress((void**)&wf, g_wf);
    cudaGetSymbolAddress((void**)&woh,g_woh);
    cudaGetSymbolAddress((void**)&qh, g_qh);
    cudaGetSymbolAddress((void**)&kh, g_kh);
    cudaGetSymbolAddress((void**)&vh, g_vh);
    cudaGetSymbolAddress((void**)&aoh,g_aoh);

    conv_all<<<14336, 256>>>(X, Wq, Wk, Wv, Wo, xh, wf, woh);

    cudaFuncSetAttribute(gemm_qkv, cudaFuncAttributeMaxDynamicSharedMemorySize, GSMEM64);
    gemm_qkv<<<296, 256, GSMEM64>>>(xh, wf, qh, kh, vh);

    cudaFuncSetAttribute(attn_mma, cudaFuncAttributeMaxDynamicSharedMemorySize, ASMEM);
    attn_mma<<<dim3(S_LEN/128, NH, 2), 256, ASMEM>>>(qh, kh, vh, aoh);

    cudaFuncSetAttribute(gemm_out, cudaFuncAttributeMaxDynamicSharedMemorySize, GSMEM64);
    gemm_out<<<296, 256, GSMEM64>>>(aoh, woh, out);
}